// round 9
// baseline (speedup 1.0000x reference)
#include <cuda_runtime.h>
#include <math.h>

#define NB 256        // batch
#define NT 64         // timesteps
#define NACT 6
#define GDIM 3072
#define ZA_LD 1040    // 1024 z + 6 act + 10 zero pad (K=1040 multiple of 16)
#define WI1_K 1040

// ---------------- scratch (device globals: no allocation allowed) ----------------
__device__ float g_ZA[NB * ZA_LD];        // [z (1024) | action (6) | zero pad]
__device__ float g_H1[NB * 1024];         // imagine hidden (post-silu)
__device__ float g_IB[NB * 2048];         // [inp (1024) | belief (1024)]
__device__ float g_HP[NB * 1024];         // prior hidden (post-silu)
__device__ float g_HO[NB * 1024];         // post hidden (post-silu)
__device__ float g_PP[4][NB * 1024];      // split-K partial pool (reused per phase)
__device__ float g_GG[2][NB * GDIM];      // gg GEMM partials
__device__ float g_Wi1p[WI1_K * 1024];    // Wi1 zero-padded to K=1040 rows
__device__ unsigned int g_cnt[128];       // per-tile split-arrival counters (self-resetting)

// ---------------- helpers ----------------
__device__ __forceinline__ float warp_sum(float v) {
#pragma unroll
    for (int o = 16; o; o >>= 1) v += __shfl_xor_sync(0xffffffffu, v, o);
    return v;
}
__device__ __forceinline__ float warp_max(float v) {
#pragma unroll
    for (int o = 16; o; o >>= 1) v = fmaxf(v, __shfl_xor_sync(0xffffffffu, v, o));
    return v;
}
__device__ __forceinline__ float silu_f(float x) {
    double e = exp(-(double)x);
    return (float)((double)x / (1.0 + e));
}
__device__ __forceinline__ float sigmoid_f(float x) {
    return (float)(1.0 / (1.0 + exp(-(double)x)));
}

__device__ __forceinline__ void cp16(void* smem, const void* g) {
    unsigned s = (unsigned)__cvta_generic_to_shared(smem);
    asm volatile("cp.async.ca.shared.global [%0], [%1], 16;\n" :: "r"(s), "l"(g));
}
__device__ __forceinline__ void cp_commit() { asm volatile("cp.async.commit_group;\n"); }
__device__ __forceinline__ void cp_wait0()  { asm volatile("cp.async.wait_group 0;\n"); }

// ---------------- init ----------------
__global__ void init_kernel(const float* __restrict__ z0, const float* __restrict__ b0,
                            const float* __restrict__ actions0) {
    int i = blockIdx.x * blockDim.x + threadIdx.x;
    if (i < 128) g_cnt[i] = 0u;
    if (i < NB * 1024) {
        int r = i >> 10, c = i & 1023;
        g_ZA[r * ZA_LD + c] = z0[i];
        g_IB[r * 2048 + 1024 + c] = b0[i];
        if (c >= 1024 - 10) g_ZA[r * ZA_LD + (c + 16)] = 0.0f;  // cols 1030..1039
        if (c < NACT) g_ZA[r * ZA_LD + 1024 + c] = actions0[r * NACT + c];
    }
}
__global__ void padw_kernel(const float* __restrict__ Wi1) {
    int i = blockIdx.x * blockDim.x + threadIdx.x;
    if (i < WI1_K * 1024) {
        int r = i >> 10;
        g_Wi1p[i] = (r < 1030) ? Wi1[i] : 0.0f;
    }
}

// ---------------- GEMM: partial product + counter-fused split-K epilogue --------
struct GP {
    const float* A;   int lda;    // k in [0, ksplit)
    const float* A2;  int lda2;   // k in [ksplit, K)
    int ksplit;
    const float* W;   int ldw;
    float* C;         int ldc;    // this split's partial buffer
    int k0, k1;                   // k-range (multiples of 16)
    // fuse info (identical for all splits of one output); D==nullptr -> no fuse
    float* D;         int ldd;
    const float* bias;
    int act;                      // 1 = silu
    int nsplit;                   // 2 or 4
    const float* P0; const float* P1; const float* P2; const float* P3;
    int ldp;
    unsigned int* counter;        // per-tile counters (gridDim.y*gridDim.x entries)
};

// BM=BN=64, BK=16, 256 threads, 4x4 microtile, double-buffered, cp.async for W.
// blockIdx.z selects one of four problem descriptors (split-K slices / pairs).
// Last split block to finish a tile performs the deterministic fixed-order
// reduction + bias + activation and writes the final output.
__global__ void __launch_bounds__(256) gemm9_kernel(GP p0, GP p1, GP p2, GP p3) {
    GP p = (blockIdx.z == 0) ? p0 : (blockIdx.z == 1) ? p1 : (blockIdx.z == 2) ? p2 : p3;
    __shared__ float As[2][16][64];
    __shared__ float Bs[2][16][64];

    const int tid = threadIdx.x;
    const int m0 = blockIdx.y * 64, n0 = blockIdx.x * 64;
    const int ar = tid & 63, ac = (tid >> 6) << 2;     // A loader: row ar, k-cols ac..ac+3
    const int br = tid >> 4, bc = (tid & 15) << 2;     // W loader: k-row br, n-cols bc..bc+3
    const int ty = tid >> 4, tx = tid & 15;

    const int t0 = p.k0 >> 4, tN = p.k1 >> 4;

    auto aptr = [&](int t) -> const float* {
        int kb = t << 4;
        return (kb < p.ksplit)
            ? p.A  + (size_t)(m0 + ar) * p.lda  + kb + ac
            : p.A2 + (size_t)(m0 + ar) * p.lda2 + (kb - p.ksplit) + ac;
    };

    float acc[4][4] = {};

    // prologue: fill buffer 0
    {
        float4 a = *(const float4*)aptr(t0);
        cp16(&Bs[0][br][bc], p.W + (size_t)(p.k0 + br) * p.ldw + n0 + bc);
        cp_commit();
        As[0][ac + 0][ar] = a.x; As[0][ac + 1][ar] = a.y;
        As[0][ac + 2][ar] = a.z; As[0][ac + 3][ar] = a.w;
        cp_wait0();
    }
    __syncthreads();

    for (int t = t0; t < tN; t++) {
        const int cur = (t - t0) & 1, nxt = cur ^ 1;
        const bool more = (t + 1) < tN;
        float4 apf;
        if (more) {
            apf = *(const float4*)aptr(t + 1);
            cp16(&Bs[nxt][br][bc], p.W + (size_t)((t + 1) * 16 + br) * p.ldw + n0 + bc);
            cp_commit();
        }
#pragma unroll
        for (int kk = 0; kk < 16; kk++) {
            float4 a = *(const float4*)&As[cur][kk][ty * 4];
            float4 b = *(const float4*)&Bs[cur][kk][tx * 4];
            acc[0][0] += a.x * b.x; acc[0][1] += a.x * b.y; acc[0][2] += a.x * b.z; acc[0][3] += a.x * b.w;
            acc[1][0] += a.y * b.x; acc[1][1] += a.y * b.y; acc[1][2] += a.y * b.z; acc[1][3] += a.y * b.w;
            acc[2][0] += a.z * b.x; acc[2][1] += a.z * b.y; acc[2][2] += a.z * b.z; acc[2][3] += a.z * b.w;
            acc[3][0] += a.w * b.x; acc[3][1] += a.w * b.y; acc[3][2] += a.w * b.z; acc[3][3] += a.w * b.w;
        }
        if (more) {
            As[nxt][ac + 0][ar] = apf.x; As[nxt][ac + 1][ar] = apf.y;
            As[nxt][ac + 2][ar] = apf.z; As[nxt][ac + 3][ar] = apf.w;
            cp_wait0();
        }
        __syncthreads();
    }

    // write this split's partial tile
#pragma unroll
    for (int i = 0; i < 4; i++) {
        const int m = m0 + ty * 4 + i;
        *(float4*)(p.C + (size_t)m * p.ldc + n0 + tx * 4) = *(float4*)&acc[i][0];
    }

    if (p.D) {
        __threadfence();              // make partials visible chip-wide (release)
        __syncthreads();              // all threads of this block stored + fenced
        __shared__ unsigned int s_last;
        unsigned int* cnt = p.counter + blockIdx.y * gridDim.x + blockIdx.x;
        if (tid == 0) s_last = atomicAdd(cnt, 1u);
        __syncthreads();
        if (s_last == (unsigned)(p.nsplit - 1)) {
            if (tid == 0) atomicExch(cnt, 0u);   // reset for next use
            __threadfence();          // acquire: see all other splits' partials
#pragma unroll
            for (int i = 0; i < 4; i++) {
                const int m = m0 + ty * 4 + i;
                const size_t off = (size_t)m * p.ldp + n0 + tx * 4;
                float4 v0 = *(const float4*)(p.P0 + off);
                float4 v1 = *(const float4*)(p.P1 + off);
                float4 o;
                if (p.nsplit == 4) {
                    float4 v2 = *(const float4*)(p.P2 + off);
                    float4 v3 = *(const float4*)(p.P3 + off);
                    o.x = (v0.x + v1.x) + (v2.x + v3.x);
                    o.y = (v0.y + v1.y) + (v2.y + v3.y);
                    o.z = (v0.z + v1.z) + (v2.z + v3.z);
                    o.w = (v0.w + v1.w) + (v2.w + v3.w);
                } else {
                    o.x = v0.x + v1.x; o.y = v0.y + v1.y;
                    o.z = v0.z + v1.z; o.w = v0.w + v1.w;
                }
                const float* b4 = p.bias + n0 + tx * 4;
                o.x += b4[0]; o.y += b4[1]; o.z += b4[2]; o.w += b4[3];
                if (p.act) { o.x = silu_f(o.x); o.y = silu_f(o.y); o.z = silu_f(o.z); o.w = silu_f(o.w); }
                *(float4*)(p.D + (size_t)m * p.ldd + n0 + tx * 4) = o;
            }
        }
    }
}

// ---------------- LayerNorm(3072, eps=1e-3) + GRU update (sums GG partials) ------
__global__ void lngru_kernel(const float* __restrict__ ln_scale, const float* __restrict__ ln_bias) {
    const int row = blockIdx.x;
    const int tid = threadIdx.x;
    __shared__ float sh[8];
    __shared__ float bcast;

    const float* g0 = g_GG[0] + (size_t)row * GDIM;
    const float* g1 = g_GG[1] + (size_t)row * GDIM;
    float x[12];
    float s = 0.0f;
#pragma unroll
    for (int i = 0; i < 12; i++) {
        x[i] = g0[tid + i * 256] + g1[tid + i * 256];
        s += x[i];
    }

    s = warp_sum(s);
    if ((tid & 31) == 0) sh[tid >> 5] = s;
    __syncthreads();
    if (tid < 32) {
        float t = (tid < 8) ? sh[tid] : 0.0f;
        t = warp_sum(t);
        if (tid == 0) bcast = t;
    }
    __syncthreads();
    const float mu = __fdiv_rn(bcast, 3072.0f);
    __syncthreads();

    float v = 0.0f;
#pragma unroll
    for (int i = 0; i < 12; i++) { float d = x[i] - mu; v += d * d; }
    v = warp_sum(v);
    if ((tid & 31) == 0) sh[tid >> 5] = v;
    __syncthreads();
    if (tid < 32) {
        float t = (tid < 8) ? sh[tid] : 0.0f;
        t = warp_sum(t);
        if (tid == 0) bcast = t;
    }
    __syncthreads();
    const float var = __fdiv_rn(bcast, 3072.0f);
    const float denom = __fsqrt_rn(var + 1e-3f);

#pragma unroll
    for (int jj = 0; jj < 4; jj++) {
        int j = tid + jj * 256;
        float yr = __fdiv_rn(x[jj]     - mu, denom) * ln_scale[j]        + ln_bias[j];
        float yc = __fdiv_rn(x[jj + 4] - mu, denom) * ln_scale[j + 1024] + ln_bias[j + 1024];
        float yu = __fdiv_rn(x[jj + 8] - mu, denom) * ln_scale[j + 2048] + ln_bias[j + 2048];
        float reset = sigmoid_f(yr);
        float cand  = (float)tanh((double)(reset * yc));
        float upd   = sigmoid_f(yu - 1.0f);   // UPDATE_BIAS = -1
        float bprev = g_IB[(size_t)row * 2048 + 1024 + j];
        float bn = upd * cand + (1.0f - upd) * bprev;
        g_IB[(size_t)row * 2048 + 1024 + j] = bn;
    }
}

// ---------------- softmax/unimix/KL + gumbel sample (sums logit partials) --------
__global__ void sample_kernel(const float* __restrict__ U_t, float* __restrict__ losses_t,
                              const float* __restrict__ bp2, const float* __restrict__ bo2,
                              const float* __restrict__ actions_next) {
    const int row = blockIdx.x;
    const int tid = threadIdx.x;
    const int warp = tid >> 5, lane = tid & 31;
    __shared__ float klsh[8];

    if (actions_next && tid < NACT)
        g_ZA[(size_t)row * ZA_LD + 1024 + tid] = actions_next[row * NACT + tid];

    float klacc = 0.0f;
#pragma unroll
    for (int sg = 0; sg < 4; sg++) {
        const int s2 = warp * 4 + sg;
        const int col = s2 * 32 + lane;
        const int idx = row * 1024 + col;

        float pl = g_PP[0][idx] + g_PP[1][idx] + bp2[col];
        float ql = g_PP[2][idx] + g_PP[3][idx] + bo2[col];
        pl = fminf(fmaxf(pl, -20.0f), 20.0f);
        ql = fminf(fmaxf(ql, -20.0f), 20.0f);

        float pm = warp_max(pl);
        float pe = (float)exp((double)(pl - pm));
        float ps = warp_sum(pe);
        float pp = __fdiv_rn(pe, ps) * 0.99f + (0.01f / 32.0f);

        float qm = warp_max(ql);
        float qe = (float)exp((double)(ql - qm));
        float qs = warp_sum(qe);
        float qp = __fdiv_rn(qe, qs) * 0.99f + (0.01f / 32.0f);

        klacc += qp * (float)(log((double)(qp + 1e-8f)) - log((double)(pp + 1e-8f)));

        float u = U_t[idx];
        float gum = (float)(-log(-log((double)u + 1e-6) + 1e-6));
        float val = (float)log((double)fmaxf(qp, 1e-6f)) + gum;
        float bv = val; int bi = lane;
#pragma unroll
        for (int o = 16; o; o >>= 1) {
            float ov = __shfl_xor_sync(0xffffffffu, bv, o);
            int   oi = __shfl_xor_sync(0xffffffffu, bi, o);
            if (ov > bv || (ov == bv && oi < bi)) { bv = ov; bi = oi; }
        }
        float y = (lane == bi) ? 1.0f : 0.0f;
        float z = __fsub_rn(__fadd_rn(y, qp), qp);
        g_ZA[(size_t)row * ZA_LD + col] = z;
    }

    float w = warp_sum(klacc);
    if (lane == 0) klsh[warp] = w;
    __syncthreads();
    if (tid == 0) {
        float kl = 0.0f;
#pragma unroll
        for (int i = 0; i < 8; i++) kl += klsh[i];
        float m = fmaxf(kl, 0.1f);
        losses_t[row] = 1.0f * m + 0.1f * m;
    }
}

// ---------------- launch ----------------
extern "C" void kernel_launch(void* const* d_in, const int* in_sizes, int n_in,
                              void* d_out, int out_size) {
    const float* b0       = (const float*)d_in[0];
    const float* z0       = (const float*)d_in[1];
    const float* actions  = (const float*)d_in[2];
    const float* obs      = (const float*)d_in[3];
    const float* u_noise  = (const float*)d_in[4];
    const float* Wi1      = (const float*)d_in[5];
    const float* bi1      = (const float*)d_in[6];
    const float* Wi2      = (const float*)d_in[7];
    const float* bi2      = (const float*)d_in[8];
    const float* Wg       = (const float*)d_in[9];
    const float* ln_scale = (const float*)d_in[10];
    const float* ln_bias  = (const float*)d_in[11];
    const float* Wo1      = (const float*)d_in[12];
    const float* bo1      = (const float*)d_in[13];
    const float* Wo2      = (const float*)d_in[14];
    const float* bo2      = (const float*)d_in[15];
    const float* Wp1      = (const float*)d_in[16];
    const float* bp1      = (const float*)d_in[17];
    const float* Wp2      = (const float*)d_in[18];
    const float* bp2      = (const float*)d_in[19];
    float* out = (float*)d_out;

    float *pZA, *pH1, *pIB, *pHP, *pHO, *pWi1p, *pPP, *pGG;
    unsigned int* pCnt;
    cudaGetSymbolAddress((void**)&pZA, g_ZA);
    cudaGetSymbolAddress((void**)&pH1, g_H1);
    cudaGetSymbolAddress((void**)&pIB, g_IB);
    cudaGetSymbolAddress((void**)&pHP, g_HP);
    cudaGetSymbolAddress((void**)&pHO, g_HO);
    cudaGetSymbolAddress((void**)&pWi1p, g_Wi1p);
    cudaGetSymbolAddress((void**)&pPP, g_PP);
    cudaGetSymbolAddress((void**)&pGG, g_GG);
    cudaGetSymbolAddress((void**)&pCnt, g_cnt);

    float* PP[4] = { pPP, pPP + NB * 1024, pPP + 2 * NB * 1024, pPP + 3 * NB * 1024 };
    float* GG[2] = { pGG, pGG + NB * GDIM };
    const float* belief = pIB + 1024;

    init_kernel<<<(NB * 1024 + 255) / 256, 256>>>(z0, b0, actions);
    padw_kernel<<<(WI1_K * 1024 + 255) / 256, 256>>>(Wi1);

    const dim3 gS4(16, 4, 4);   // N=1024, split-4 (or 2x split-2 pairs): 256 blocks
    const dim3 gG2(48, 4, 2);   // N=3072, split-2: 384 blocks

    for (int t = 0; t < NT; t++) {
        const float* obs_t = obs + (size_t)t * NB * 1024;

        // ---- imagine layer 1: ZA @ Wi1p, K=1040, split4, epilogue -> silu H1 ----
        {
            GP a{pZA, ZA_LD, pZA, ZA_LD, WI1_K, pWi1p, 1024, PP[0], 1024, 0,   272,
                 pH1, 1024, bi1, 1, 4, PP[0], PP[1], PP[2], PP[3], 1024, pCnt};
            GP b = a; b.C = PP[1]; b.k0 = 272; b.k1 = 528;
            GP c = a; c.C = PP[2]; c.k0 = 528; c.k1 = 784;
            GP d = a; d.C = PP[3]; d.k0 = 784; d.k1 = 1040;
            gemm9_kernel<<<gS4, 256>>>(a, b, c, d);
        }

        // ---- imagine layer 2: H1 @ Wi2, K=1024, split4, epilogue -> IB[:, :1024] ----
        {
            GP a{pH1, 1024, pH1, 1024, 1024, Wi2, 1024, PP[0], 1024, 0,   256,
                 pIB, 2048, bi2, 0, 4, PP[0], PP[1], PP[2], PP[3], 1024, pCnt};
            GP b = a; b.C = PP[1]; b.k0 = 256; b.k1 = 512;
            GP c = a; c.C = PP[2]; c.k0 = 512; c.k1 = 768;
            GP d = a; d.C = PP[3]; d.k0 = 768; d.k1 = 1024;
            gemm9_kernel<<<gS4, 256>>>(a, b, c, d);
        }

        // ---- GRU gates: IB @ Wg, K=2048, N=3072, split2 (no fuse; lngru sums) ----
        {
            GP a{pIB, 2048, pIB, 2048, 2048, Wg, 3072, GG[0], 3072, 0,    1024,
                 nullptr, 0, nullptr, 0, 0, nullptr, nullptr, nullptr, nullptr, 0, nullptr};
            GP b = a; b.C = GG[1]; b.k0 = 1024; b.k1 = 2048;
            gemm9_kernel<<<gG2, 256>>>(a, b, a, b);
        }
        lngru_kernel<<<NB, 256>>>(ln_scale, ln_bias);

        // ---- prior L1 (split2 -> silu HP) || posterior L1 (split2 -> silu HO) ----
        {
            GP a{belief, 2048, belief, 2048, 1024, Wp1, 1024, PP[0], 1024, 0,   512,
                 pHP, 1024, bp1, 1, 2, PP[0], PP[1], nullptr, nullptr, 1024, pCnt};
            GP b = a; b.C = PP[1]; b.k0 = 512; b.k1 = 1024;
            GP c{obs_t, 1024, belief, 2048, 1024, Wo1, 1024, PP[2], 1024, 0,    1024,
                 pHO, 1024, bo1, 1, 2, PP[2], PP[3], nullptr, nullptr, 1024, pCnt + 64};
            GP d = c; d.C = PP[3]; d.k0 = 1024; d.k1 = 2048;
            gemm9_kernel<<<gS4, 256>>>(a, b, c, d);
        }

        // ---- prior L2 (split2) || posterior L2 (split2): partials only ----
        {
            GP a{pHP, 1024, pHP, 1024, 1024, Wp2, 1024, PP[0], 1024, 0,   512,
                 nullptr, 0, nullptr, 0, 0, nullptr, nullptr, nullptr, nullptr, 0, nullptr};
            GP b = a; b.C = PP[1]; b.k0 = 512; b.k1 = 1024;
            GP c = a; c.A = pHO; c.A2 = pHO; c.W = Wo2; c.C = PP[2]; c.k0 = 0; c.k1 = 512;
            GP d = c; d.C = PP[3]; d.k0 = 512; d.k1 = 1024;
            gemm9_kernel<<<gS4, 256>>>(a, b, c, d);
        }

        // ---- probs + KL + gumbel sample (+ stage next actions) ----
        const float* an = (t + 1 < NT) ? (actions + (size_t)(t + 1) * NB * NACT) : nullptr;
        sample_kernel<<<NB, 256>>>(u_noise + (size_t)t * NB * 1024, out + (size_t)t * NB,
                                   bp2, bo2, an);
    }
}

// round 11
// speedup vs baseline: 1.1963x; 1.1963x over previous
#include <cuda_runtime.h>
#include <math.h>

#define NB 256        // batch
#define NT 64         // timesteps
#define NACT 6
#define GDIM 3072
#define ZA_LD 1040    // 1024 z + 6 act + 10 zero pad (K=1040 multiple of 16)
#define WI1_K 1040

// ---------------- scratch (device globals: no allocation allowed) ----------------
__device__ float g_ZA[NB * ZA_LD];        // [z (1024) | action (6) | zero pad]
__device__ float g_H1[NB * 1024];         // imagine hidden (post-silu)
__device__ float g_IB[NB * 2048];         // [inp (1024) | belief (1024)]
__device__ float g_HP[NB * 1024];         // prior hidden (post-silu)
__device__ float g_HO[NB * 1024];         // post hidden (post-silu)
__device__ float g_PP[8][NB * 1024];      // split-K partial pool (reused per phase)
__device__ float g_GG[4][NB * GDIM];      // gg GEMM partials
__device__ float g_Wi1p[WI1_K * 1024];    // Wi1 zero-padded to K=1040 rows

// ---------------- helpers ----------------
__device__ __forceinline__ float warp_sum(float v) {
#pragma unroll
    for (int o = 16; o; o >>= 1) v += __shfl_xor_sync(0xffffffffu, v, o);
    return v;
}
__device__ __forceinline__ float warp_max(float v) {
#pragma unroll
    for (int o = 16; o; o >>= 1) v = fmaxf(v, __shfl_xor_sync(0xffffffffu, v, o));
    return v;
}
__device__ __forceinline__ float silu_f(float x) {
    double e = exp(-(double)x);
    return (float)((double)x / (1.0 + e));
}
__device__ __forceinline__ float sigmoid_f(float x) {
    return (float)(1.0 / (1.0 + exp(-(double)x)));
}

__device__ __forceinline__ void cp16(void* smem, const void* g) {
    unsigned s = (unsigned)__cvta_generic_to_shared(smem);
    asm volatile("cp.async.ca.shared.global [%0], [%1], 16;\n" :: "r"(s), "l"(g));
}
__device__ __forceinline__ void cp_commit() { asm volatile("cp.async.commit_group;\n"); }
__device__ __forceinline__ void cp_wait0()  { asm volatile("cp.async.wait_group 0;\n"); }

// ---------------- init ----------------
__global__ void init_kernel(const float* __restrict__ z0, const float* __restrict__ b0,
                            const float* __restrict__ actions0) {
    int i = blockIdx.x * blockDim.x + threadIdx.x;
    if (i < NB * 1024) {
        int r = i >> 10, c = i & 1023;
        g_ZA[r * ZA_LD + c] = z0[i];
        g_IB[r * 2048 + 1024 + c] = b0[i];
        if (c >= 1024 - 10) g_ZA[r * ZA_LD + (c + 16)] = 0.0f;  // cols 1030..1039
        if (c < NACT) g_ZA[r * ZA_LD + 1024 + c] = actions0[r * NACT + c];
    }
}
__global__ void padw_kernel(const float* __restrict__ Wi1) {
    int i = blockIdx.x * blockDim.x + threadIdx.x;
    if (i < WI1_K * 1024) {
        int r = i >> 10;
        g_Wi1p[i] = (r < 1030) ? Wi1[i] : 0.0f;
    }
}

// ---------------- GEMM problem descriptor: z-slice -> k-range ----------------
// slice s = blockIdx.z - zlo; k0(s) = (s==0) ? 0 : kfe + (s-1)*kstep;
// k1(s) = kfe + s*kstep; partial out = C + s*cstride.
struct GP {
    const float* A;   int lda;    // k in [0, ksplit)
    const float* A2;  int lda2;   // k in [ksplit, K)
    int ksplit;
    const float* W;   int ldw;
    float* C;         int ldc;
    long long cstride;            // elements between split partial buffers
    int zlo;                      // first z owned by this problem
    int kfe;                      // end of first slice
    int kstep;                    // size of subsequent slices
};

// C_partial = A[k0:k1] @ W[k0:k1]. BM=BN=64, BK=16, 256 threads, 4x4 microtile,
// double-buffered, cp.async for W. blockIdx.z picks problem (zlo) + k-slice.
__global__ void __launch_bounds__(256) gemm10_kernel(GP p0, GP p1) {
    GP p = (blockIdx.z >= (unsigned)p1.zlo) ? p1 : p0;
    const int s = blockIdx.z - p.zlo;
    const int k0 = (s == 0) ? 0 : p.kfe + (s - 1) * p.kstep;
    const int k1 = p.kfe + s * p.kstep;
    float* Cout = p.C + (long long)s * p.cstride;

    __shared__ float As[2][16][64];
    __shared__ float Bs[2][16][64];

    const int tid = threadIdx.x;
    const int m0 = blockIdx.y * 64, n0 = blockIdx.x * 64;
    const int ar = tid & 63, ac = (tid >> 6) << 2;     // A loader: row ar, k-cols ac..ac+3
    const int br = tid >> 4, bc = (tid & 15) << 2;     // W loader: k-row br, n-cols bc..bc+3
    const int ty = tid >> 4, tx = tid & 15;

    const int t0 = k0 >> 4, tN = k1 >> 4;

    auto aptr = [&](int t) -> const float* {
        int kb = t << 4;
        return (kb < p.ksplit)
            ? p.A  + (size_t)(m0 + ar) * p.lda  + kb + ac
            : p.A2 + (size_t)(m0 + ar) * p.lda2 + (kb - p.ksplit) + ac;
    };

    float acc[4][4] = {};

    // prologue: fill buffer 0
    {
        float4 a = *(const float4*)aptr(t0);
        cp16(&Bs[0][br][bc], p.W + (size_t)(k0 + br) * p.ldw + n0 + bc);
        cp_commit();
        As[0][ac + 0][ar] = a.x; As[0][ac + 1][ar] = a.y;
        As[0][ac + 2][ar] = a.z; As[0][ac + 3][ar] = a.w;
        cp_wait0();
    }
    __syncthreads();

    for (int t = t0; t < tN; t++) {
        const int cur = (t - t0) & 1, nxt = cur ^ 1;
        const bool more = (t + 1) < tN;
        float4 apf;
        if (more) {
            apf = *(const float4*)aptr(t + 1);
            cp16(&Bs[nxt][br][bc], p.W + (size_t)((t + 1) * 16 + br) * p.ldw + n0 + bc);
            cp_commit();
        }
#pragma unroll
        for (int kk = 0; kk < 16; kk++) {
            float4 a = *(const float4*)&As[cur][kk][ty * 4];
            float4 b = *(const float4*)&Bs[cur][kk][tx * 4];
            acc[0][0] += a.x * b.x; acc[0][1] += a.x * b.y; acc[0][2] += a.x * b.z; acc[0][3] += a.x * b.w;
            acc[1][0] += a.y * b.x; acc[1][1] += a.y * b.y; acc[1][2] += a.y * b.z; acc[1][3] += a.y * b.w;
            acc[2][0] += a.z * b.x; acc[2][1] += a.z * b.y; acc[2][2] += a.z * b.z; acc[2][3] += a.z * b.w;
            acc[3][0] += a.w * b.x; acc[3][1] += a.w * b.y; acc[3][2] += a.w * b.z; acc[3][3] += a.w * b.w;
        }
        if (more) {
            As[nxt][ac + 0][ar] = apf.x; As[nxt][ac + 1][ar] = apf.y;
            As[nxt][ac + 2][ar] = apf.z; As[nxt][ac + 3][ar] = apf.w;
            cp_wait0();
        }
        __syncthreads();
    }

#pragma unroll
    for (int i = 0; i < 4; i++) {
        const int m = m0 + ty * 4 + i;
        *(float4*)(Cout + (size_t)m * p.ldc + n0 + tx * 4) = *(float4*)&acc[i][0];
    }
}

// ---------------- fuse8: out = [silu](sum PP[0..7] + bias) ----------------------
// grid: 256 blocks x 256 threads x float4 = 262144 floats
__global__ void fuse8_kernel(const float* __restrict__ bias, float* __restrict__ out,
                             int ldo, int dsilu) {
    int i = (blockIdx.x * blockDim.x + threadIdx.x) << 2;
    int r = i >> 10, c = i & 1023;
    float4 o = *(const float4*)&g_PP[0][i];
#pragma unroll
    for (int s = 1; s < 8; s++) {
        float4 v = *(const float4*)&g_PP[s][i];
        o.x += v.x; o.y += v.y; o.z += v.z; o.w += v.w;
    }
    float4 b4 = *(const float4*)&bias[c];
    o.x += b4.x; o.y += b4.y; o.z += b4.z; o.w += b4.w;
    if (dsilu) { o.x = silu_f(o.x); o.y = silu_f(o.y); o.z = silu_f(o.z); o.w = silu_f(o.w); }
    *(float4*)(out + (size_t)r * ldo + c) = o;
}

// ---------------- fuse44: HP = silu(PP[0..3]+bp1), HO = silu(PP[4..7]+bo1) -------
__global__ void fuse44_kernel(const float* __restrict__ bp1, const float* __restrict__ bo1) {
    int i = (blockIdx.x * blockDim.x + threadIdx.x) << 2;
    int c = i & 1023;
    const int base = blockIdx.y * 4;
    const float* bias = blockIdx.y ? bo1 : bp1;
    float* out = blockIdx.y ? g_HO : g_HP;
    float4 o = *(const float4*)&g_PP[base][i];
#pragma unroll
    for (int s = 1; s < 4; s++) {
        float4 v = *(const float4*)&g_PP[base + s][i];
        o.x += v.x; o.y += v.y; o.z += v.z; o.w += v.w;
    }
    float4 b4 = *(const float4*)&bias[c];
    o.x = silu_f(o.x + b4.x);
    o.y = silu_f(o.y + b4.y);
    o.z = silu_f(o.z + b4.z);
    o.w = silu_f(o.w + b4.w);
    *(float4*)(out + i) = o;
}

// ---------------- LayerNorm(3072, eps=1e-3) + GRU update (sums 4 GG partials) ----
__global__ void lngru_kernel(const float* __restrict__ ln_scale, const float* __restrict__ ln_bias) {
    const int row = blockIdx.x;
    const int tid = threadIdx.x;
    __shared__ float sh[8];
    __shared__ float bcast;

    const float* g0 = g_GG[0] + (size_t)row * GDIM;
    const float* g1 = g_GG[1] + (size_t)row * GDIM;
    const float* g2 = g_GG[2] + (size_t)row * GDIM;
    const float* g3 = g_GG[3] + (size_t)row * GDIM;
    float x[12];
    float s = 0.0f;
#pragma unroll
    for (int i = 0; i < 12; i++) {
        int j = tid + i * 256;
        x[i] = ((g0[j] + g1[j]) + (g2[j] + g3[j]));
        s += x[i];
    }

    s = warp_sum(s);
    if ((tid & 31) == 0) sh[tid >> 5] = s;
    __syncthreads();
    if (tid < 32) {
        float t = (tid < 8) ? sh[tid] : 0.0f;
        t = warp_sum(t);
        if (tid == 0) bcast = t;
    }
    __syncthreads();
    const float mu = __fdiv_rn(bcast, 3072.0f);
    __syncthreads();

    float v = 0.0f;
#pragma unroll
    for (int i = 0; i < 12; i++) { float d = x[i] - mu; v += d * d; }
    v = warp_sum(v);
    if ((tid & 31) == 0) sh[tid >> 5] = v;
    __syncthreads();
    if (tid < 32) {
        float t = (tid < 8) ? sh[tid] : 0.0f;
        t = warp_sum(t);
        if (tid == 0) bcast = t;
    }
    __syncthreads();
    const float var = __fdiv_rn(bcast, 3072.0f);
    const float denom = __fsqrt_rn(var + 1e-3f);

#pragma unroll
    for (int jj = 0; jj < 4; jj++) {
        int j = tid + jj * 256;
        float yr = __fdiv_rn(x[jj]     - mu, denom) * ln_scale[j]        + ln_bias[j];
        float yc = __fdiv_rn(x[jj + 4] - mu, denom) * ln_scale[j + 1024] + ln_bias[j + 1024];
        float yu = __fdiv_rn(x[jj + 8] - mu, denom) * ln_scale[j + 2048] + ln_bias[j + 2048];
        float reset = sigmoid_f(yr);
        float cand  = (float)tanh((double)(reset * yc));
        float upd   = sigmoid_f(yu - 1.0f);   // UPDATE_BIAS = -1
        float bprev = g_IB[(size_t)row * 2048 + 1024 + j];
        float bn = upd * cand + (1.0f - upd) * bprev;
        g_IB[(size_t)row * 2048 + 1024 + j] = bn;
    }
}

// ---------------- softmax/unimix/KL + gumbel sample (sums 4+4 logit partials) ----
__global__ void sample_kernel(const float* __restrict__ U_t, float* __restrict__ losses_t,
                              const float* __restrict__ bp2, const float* __restrict__ bo2,
                              const float* __restrict__ actions_next) {
    const int row = blockIdx.x;
    const int tid = threadIdx.x;
    const int warp = tid >> 5, lane = tid & 31;
    __shared__ float klsh[8];

    if (actions_next && tid < NACT)
        g_ZA[(size_t)row * ZA_LD + 1024 + tid] = actions_next[row * NACT + tid];

    float klacc = 0.0f;
#pragma unroll
    for (int sg = 0; sg < 4; sg++) {
        const int s2 = warp * 4 + sg;
        const int col = s2 * 32 + lane;
        const int idx = row * 1024 + col;

        float pl = ((g_PP[0][idx] + g_PP[1][idx]) + (g_PP[2][idx] + g_PP[3][idx])) + bp2[col];
        float ql = ((g_PP[4][idx] + g_PP[5][idx]) + (g_PP[6][idx] + g_PP[7][idx])) + bo2[col];
        pl = fminf(fmaxf(pl, -20.0f), 20.0f);
        ql = fminf(fmaxf(ql, -20.0f), 20.0f);

        float pm = warp_max(pl);
        float pe = (float)exp((double)(pl - pm));
        float ps = warp_sum(pe);
        float pp = __fdiv_rn(pe, ps) * 0.99f + (0.01f / 32.0f);

        float qm = warp_max(ql);
        float qe = (float)exp((double)(ql - qm));
        float qs = warp_sum(qe);
        float qp = __fdiv_rn(qe, qs) * 0.99f + (0.01f / 32.0f);

        klacc += qp * (float)(log((double)(qp + 1e-8f)) - log((double)(pp + 1e-8f)));

        float u = U_t[idx];
        float gum = (float)(-log(-log((double)u + 1e-6) + 1e-6));
        float val = (float)log((double)fmaxf(qp, 1e-6f)) + gum;
        float bv = val; int bi = lane;
#pragma unroll
        for (int o = 16; o; o >>= 1) {
            float ov = __shfl_xor_sync(0xffffffffu, bv, o);
            int   oi = __shfl_xor_sync(0xffffffffu, bi, o);
            if (ov > bv || (ov == bv && oi < bi)) { bv = ov; bi = oi; }
        }
        float y = (lane == bi) ? 1.0f : 0.0f;
        float z = __fsub_rn(__fadd_rn(y, qp), qp);
        g_ZA[(size_t)row * ZA_LD + col] = z;
    }

    float w = warp_sum(klacc);
    if (lane == 0) klsh[warp] = w;
    __syncthreads();
    if (tid == 0) {
        float kl = 0.0f;
#pragma unroll
        for (int i = 0; i < 8; i++) kl += klsh[i];
        float m = fmaxf(kl, 0.1f);
        losses_t[row] = 1.0f * m + 0.1f * m;
    }
}

// ---------------- launch ----------------
extern "C" void kernel_launch(void* const* d_in, const int* in_sizes, int n_in,
                              void* d_out, int out_size) {
    const float* b0       = (const float*)d_in[0];
    const float* z0       = (const float*)d_in[1];
    const float* actions  = (const float*)d_in[2];
    const float* obs      = (const float*)d_in[3];
    const float* u_noise  = (const float*)d_in[4];
    const float* Wi1      = (const float*)d_in[5];
    const float* bi1      = (const float*)d_in[6];
    const float* Wi2      = (const float*)d_in[7];
    const float* bi2      = (const float*)d_in[8];
    const float* Wg       = (const float*)d_in[9];
    const float* ln_scale = (const float*)d_in[10];
    const float* ln_bias  = (const float*)d_in[11];
    const float* Wo1      = (const float*)d_in[12];
    const float* bo1      = (const float*)d_in[13];
    const float* Wo2      = (const float*)d_in[14];
    const float* bo2      = (const float*)d_in[15];
    const float* Wp1      = (const float*)d_in[16];
    const float* bp1      = (const float*)d_in[17];
    const float* Wp2      = (const float*)d_in[18];
    const float* bp2      = (const float*)d_in[19];
    float* out = (float*)d_out;

    float *pZA, *pH1, *pIB, *pHP, *pHO, *pWi1p, *pPP, *pGG;
    cudaGetSymbolAddress((void**)&pZA, g_ZA);
    cudaGetSymbolAddress((void**)&pH1, g_H1);
    cudaGetSymbolAddress((void**)&pIB, g_IB);
    cudaGetSymbolAddress((void**)&pHP, g_HP);
    cudaGetSymbolAddress((void**)&pHO, g_HO);
    cudaGetSymbolAddress((void**)&pWi1p, g_Wi1p);
    cudaGetSymbolAddress((void**)&pPP, g_PP);
    cudaGetSymbolAddress((void**)&pGG, g_GG);

    const long long PSTRIDE = (long long)NB * 1024;
    const long long GSTRIDE = (long long)NB * GDIM;
    const float* belief = pIB + 1024;

    init_kernel<<<(NB * 1024 + 255) / 256, 256>>>(z0, b0, actions);
    padw_kernel<<<(WI1_K * 1024 + 255) / 256, 256>>>(Wi1);

    const dim3 gS8(16, 4, 8);   // N=1024, 8 slices total: 512 blocks
    const dim3 gG4(48, 4, 4);   // N=3072, split-4: 768 blocks
    const dim3 gF(256, 1, 1);
    const dim3 gF2(256, 2, 1);

    for (int t = 0; t < NT; t++) {
        const float* obs_t = obs + (size_t)t * NB * 1024;

        // ---- imagine layer 1: ZA @ Wi1p, K=1040, split-8 (144 + 7x128) ----
        {
            GP a{pZA, ZA_LD, pZA, ZA_LD, WI1_K, pWi1p, 1024, pPP, 1024, PSTRIDE, 0, 144, 128};
            gemm10_kernel<<<gS8, 256>>>(a, a);
        }
        fuse8_kernel<<<gF, 256>>>(bi1, pH1, 1024, 1);

        // ---- imagine layer 2: H1 @ Wi2, K=1024, split-8 ----
        {
            GP a{pH1, 1024, pH1, 1024, 1024, Wi2, 1024, pPP, 1024, PSTRIDE, 0, 128, 128};
            gemm10_kernel<<<gS8, 256>>>(a, a);
        }
        fuse8_kernel<<<gF, 256>>>(bi2, pIB, 2048, 0);

        // ---- GRU gates: IB @ Wg, K=2048, N=3072, split-4 ----
        {
            GP a{pIB, 2048, pIB, 2048, 2048, Wg, 3072, pGG, 3072, GSTRIDE, 0, 512, 512};
            gemm10_kernel<<<gG4, 256>>>(a, a);
        }
        lngru_kernel<<<NB, 256>>>(ln_scale, ln_bias);

        // ---- prior L1 split-4 (z 0..3) || posterior L1 split-4 (z 4..7) ----
        {
            GP a{belief, 2048, belief, 2048, 1024, Wp1, 1024, pPP, 1024, PSTRIDE, 0, 256, 256};
            GP b{obs_t,  1024, belief, 2048, 1024, Wo1, 1024, pPP + 4 * PSTRIDE, 1024, PSTRIDE, 4, 512, 512};
            gemm10_kernel<<<gS8, 256>>>(a, b);
        }
        fuse44_kernel<<<gF2, 256>>>(bp1, bo1);

        // ---- prior L2 split-4 || posterior L2 split-4 ----
        {
            GP a{pHP, 1024, pHP, 1024, 1024, Wp2, 1024, pPP, 1024, PSTRIDE, 0, 256, 256};
            GP b{pHO, 1024, pHO, 1024, 1024, Wo2, 1024, pPP + 4 * PSTRIDE, 1024, PSTRIDE, 4, 256, 256};
            gemm10_kernel<<<gS8, 256>>>(a, b);
        }

        // ---- probs + KL + gumbel sample (+ stage next actions) ----
        const float* an = (t + 1 < NT) ? (actions + (size_t)(t + 1) * NB * NACT) : nullptr;
        sample_kernel<<<NB, 256>>>(u_noise + (size_t)t * NB * 1024, out + (size_t)t * NB,
                                   bp2, bo2, an);
    }
}